// round 1
// baseline (speedup 1.0000x reference)
#include <cuda_runtime.h>
#include <math.h>

// Problem constants (fixed by the reference)
#define BSZ   16
#define GR    52
#define HH    256
#define WW    256
#define HW    (HH * WW)          // 65536 elements per (b,g) plane
#define NT    512                // threads per block (== HH + WW, used for LUT fill)
#define NW    (NT / 32)          // warps per block = 16
#define ITERS (HW / (NT * 4))    // 32 float4 iterations per pass

__global__ __launch_bounds__(NT)
void prm_kernel(const float* __restrict__ x,
                const float* __restrict__ wgt,    // [GR]
                const float* __restrict__ bias,   // [GR]
                const float* __restrict__ one,    // [GR]
                const float* __restrict__ zero,   // [GR]
                const float* __restrict__ theta,  // [2]
                const float* __restrict__ scale,  // [1]
                float* __restrict__ out)
{
    const int p    = blockIdx.x;          // plane index = b*GR + g
    const int g    = p % GR;
    const int tid  = threadIdx.x;
    const int lane = tid & 31;
    const int wid  = tid >> 5;

    const float4* x4 = (const float4*)x + (size_t)p * (HW / 4);
    float4*       o4 = (float4*)out     + (size_t)p * (HW / 4);

    __shared__ __align__(16) float grow[HH];
    __shared__ __align__(16) float gcol[WW];
    __shared__ float r0[NW], r1[NW], r2[NW];
    __shared__ int   ri[NW];
    __shared__ float bc[8];

    // ---------------- Pass 1: argmax(first-occurrence), sum, sumsq -------------
    float bv = -3.402823466e38f;
    int   bi = 0x7fffffff;
    float s  = 0.f, s2 = 0.f;

    #pragma unroll 4
    for (int it = 0; it < ITERS; ++it) {
        int    idx4 = it * NT + tid;
        float4 v    = x4[idx4];
        int    i0   = idx4 << 2;
        s  += (v.x + v.y) + (v.z + v.w);
        s2 += (v.x * v.x + v.y * v.y) + (v.z * v.z + v.w * v.w);
        // ascending index scan + strict '>' keeps first occurrence within thread
        if (v.x > bv) { bv = v.x; bi = i0;     }
        if (v.y > bv) { bv = v.y; bi = i0 + 1; }
        if (v.z > bv) { bv = v.z; bi = i0 + 2; }
        if (v.w > bv) { bv = v.w; bi = i0 + 3; }
    }

    // warp reduction
    #pragma unroll
    for (int o = 16; o; o >>= 1) {
        s  += __shfl_down_sync(0xffffffffu, s,  o);
        s2 += __shfl_down_sync(0xffffffffu, s2, o);
        float ov = __shfl_down_sync(0xffffffffu, bv, o);
        int   oi = __shfl_down_sync(0xffffffffu, bi, o);
        if (ov > bv || (ov == bv && oi < bi)) { bv = ov; bi = oi; }
    }
    if (lane == 0) { r0[wid] = s; r1[wid] = s2; r2[wid] = bv; ri[wid] = bi; }
    __syncthreads();

    if (wid == 0) {
        s  = (lane < NW) ? r0[lane] : 0.f;
        s2 = (lane < NW) ? r1[lane] : 0.f;
        bv = (lane < NW) ? r2[lane] : -3.402823466e38f;
        bi = (lane < NW) ? ri[lane] : 0x7fffffff;
        #pragma unroll
        for (int o = 16; o; o >>= 1) {
            s  += __shfl_down_sync(0xffffffffu, s,  o);
            s2 += __shfl_down_sync(0xffffffffu, s2, o);
            float ov = __shfl_down_sync(0xffffffffu, bv, o);
            int   oi = __shfl_down_sync(0xffffffffu, bi, o);
            if (ov > bv || (ov == bv && oi < bi)) { bv = ov; bi = oi; }
        }
        if (lane == 0) {
            bc[0] = (float)(bi >> 8);   // qrow  (W = 256)
            bc[1] = (float)(bi & 255);  // qcol
            bc[2] = bv;                 // qval
            bc[3] = s * (1.0f / (float)HW); // gap (plane mean)
            bc[4] = s;                  // Sx
            bc[5] = s2;                 // Sx2
        }
    }
    __syncthreads();

    // ---------------- Gaussian LUTs (separable dist) ----------------------------
    {
        float sigma  = scale[0];
        float ln     = -logf(sigma) - 0.91893853320467274f;  // -log(sigma) - 0.5*log(2*pi)
        float inv2s2 = 0.5f / (sigma * sigma);
        if (tid < HH) {
            float d = fabsf((float)tid - bc[0]) * theta[0];
            grow[tid] = __expf(ln - d * d * inv2s2);
        } else {                         // NT == HH + WW
            int   c = tid - HH;
            float d = fabsf((float)c - bc[1]) * theta[1];
            gcol[c] = __expf(ln - d * d * inv2s2);
        }
    }
    __syncthreads();

    // ---------------- Pass 2: Σ x·d, Σ x²·d, Σ x²·d² ---------------------------
    float sxd = 0.f, sx2d = 0.f, sx2d2 = 0.f;
    #pragma unroll 4
    for (int it = 0; it < ITERS; ++it) {
        int    idx4 = it * NT + tid;
        float4 v    = x4[idx4];
        int    i0   = idx4 << 2;
        float  gr   = grow[i0 >> 8];
        float4 gc   = *(const float4*)&gcol[i0 & 255];  // i0 % 4 == 0
        float d0 = 0.5f * (gr + gc.x);
        float d1 = 0.5f * (gr + gc.y);
        float d2 = 0.5f * (gr + gc.z);
        float d3 = 0.5f * (gr + gc.w);
        sxd   += v.x * d0 + v.y * d1 + v.z * d2 + v.w * d3;
        float q0 = v.x * v.x, q1 = v.y * v.y, q2 = v.z * v.z, q3 = v.w * v.w;
        sx2d  += q0 * d0 + q1 * d1 + q2 * d2 + q3 * d3;
        sx2d2 += q0 * d0 * d0 + q1 * d1 * d1 + q2 * d2 * d2 + q3 * d3 * d3;
    }
    #pragma unroll
    for (int o = 16; o; o >>= 1) {
        sxd   += __shfl_down_sync(0xffffffffu, sxd,   o);
        sx2d  += __shfl_down_sync(0xffffffffu, sx2d,  o);
        sx2d2 += __shfl_down_sync(0xffffffffu, sx2d2, o);
    }
    if (lane == 0) { r0[wid] = sxd; r1[wid] = sx2d; r2[wid] = sx2d2; }
    __syncthreads();

    if (wid == 0) {
        sxd   = (lane < NW) ? r0[lane] : 0.f;
        sx2d  = (lane < NW) ? r1[lane] : 0.f;
        sx2d2 = (lane < NW) ? r2[lane] : 0.f;
        #pragma unroll
        for (int o = 16; o; o >>= 1) {
            sxd   += __shfl_down_sync(0xffffffffu, sxd,   o);
            sx2d  += __shfl_down_sync(0xffffffffu, sx2d,  o);
            sx2d2 += __shfl_down_sync(0xffffffffu, sx2d2, o);
        }
        if (lane == 0) {
            float A  = bc[2] * zero[g];       // qval * zero[g]
            float Bc = bc[3] * one[g];        // gap  * one[g]
            float Ssim  = A * sxd + Bc * bc[4];
            float Ssim2 = A * A * sx2d2 + 2.f * A * Bc * sx2d + Bc * Bc * bc[5];
            float mean  = Ssim * (1.0f / (float)HW);
            float var   = (Ssim2 - Ssim * Ssim * (1.0f / (float)HW)) * (1.0f / (float)(HW - 1));
            float sd    = sqrtf(fmaxf(var, 0.f)) + 1e-5f;
            bc[0] = A;
            bc[1] = Bc;
            bc[2] = mean;
            bc[3] = wgt[g] / sd;              // fold /std into weight
            bc[4] = bias[g];
        }
    }
    __syncthreads();

    // ---------------- Pass 3: gated output -------------------------------------
    {
        float A  = bc[0], Bc = bc[1], mean = bc[2], k1 = bc[3], b0 = bc[4];
        #pragma unroll 4
        for (int it = 0; it < ITERS; ++it) {
            int    idx4 = it * NT + tid;
            float4 v    = x4[idx4];
            int    i0   = idx4 << 2;
            float  gr   = grow[i0 >> 8];
            float4 gc   = *(const float4*)&gcol[i0 & 255];
            float d0 = 0.5f * (gr + gc.x);
            float d1 = 0.5f * (gr + gc.y);
            float d2 = 0.5f * (gr + gc.z);
            float d3 = 0.5f * (gr + gc.w);
            float t0 = (v.x * (A * d0 + Bc) - mean) * k1 + b0;
            float t1 = (v.y * (A * d1 + Bc) - mean) * k1 + b0;
            float t2 = (v.z * (A * d2 + Bc) - mean) * k1 + b0;
            float t3 = (v.w * (A * d3 + Bc) - mean) * k1 + b0;
            float4 o;
            o.x = v.x / (1.f + __expf(-t0));
            o.y = v.y / (1.f + __expf(-t1));
            o.z = v.z / (1.f + __expf(-t2));
            o.w = v.w / (1.f + __expf(-t3));
            o4[idx4] = o;
        }
    }
}

extern "C" void kernel_launch(void* const* d_in, const int* in_sizes, int n_in,
                              void* d_out, int out_size)
{
    const float* x     = (const float*)d_in[0];  // [16,52,256,256]
    const float* wgt   = (const float*)d_in[1];  // [1,52,1,1]
    const float* bias  = (const float*)d_in[2];  // [1,52,1,1]
    const float* one   = (const float*)d_in[3];  // [1,52,1]
    const float* zero  = (const float*)d_in[4];  // [1,52,1]
    const float* theta = (const float*)d_in[5];  // [1,2,1,1]
    const float* scale = (const float*)d_in[6];  // [1]
    float* out = (float*)d_out;

    prm_kernel<<<BSZ * GR, NT>>>(x, wgt, bias, one, zero, theta, scale, out);
}